// round 1
// baseline (speedup 1.0000x reference)
#include <cuda_runtime.h>
#include <cuda_bf16.h>

// LIF recurrence over T=4 steps.
// x: [T=4, B=64, C=128, H=32, W=32] fp32
// mem0: [1, C, H, W] fp32, broadcast over B
// out (spikes): [T, B, C, H, W] fp32 in {0,1}
//
// Per element: mem = tau*mem + x[t]; s = (mem > v_th); mem = s ? 0 : mem.
// Each thread handles 4 consecutive elements (float4) and loops t in regs.

#define TAU 0.25f
#define V_TH 1.0f

__global__ __launch_bounds__(256) void lif_kernel(
    const float4* __restrict__ x,
    const float4* __restrict__ mem0,
    float4* __restrict__ out,
    int n4)          // n4 = B*C*H*W/4 elements per timestep (float4 units)
{
    int i = blockIdx.x * blockDim.x + threadIdx.x;
    if (i >= n4) return;

    // CHW/4 = 128*32*32/4 = 32768 = 2^15 -> cheap mask for the B-broadcast
    const int CHW4_MASK = 32767;
    float4 mem = mem0[i & CHW4_MASK];

    // Load all 4 timesteps up front: addresses are independent of mem,
    // so the 4 LDG.128 issue back-to-back (MLP=4).
    float4 x0 = x[0 * (size_t)n4 + i];
    float4 x1 = x[1 * (size_t)n4 + i];
    float4 x2 = x[2 * (size_t)n4 + i];
    float4 x3 = x[3 * (size_t)n4 + i];

    float4 s;

    // t = 0
    mem.x = TAU * mem.x + x0.x; s.x = (mem.x > V_TH) ? 1.0f : 0.0f; mem.x = (mem.x > V_TH) ? 0.0f : mem.x;
    mem.y = TAU * mem.y + x0.y; s.y = (mem.y > V_TH) ? 1.0f : 0.0f; mem.y = (mem.y > V_TH) ? 0.0f : mem.y;
    mem.z = TAU * mem.z + x0.z; s.z = (mem.z > V_TH) ? 1.0f : 0.0f; mem.z = (mem.z > V_TH) ? 0.0f : mem.z;
    mem.w = TAU * mem.w + x0.w; s.w = (mem.w > V_TH) ? 1.0f : 0.0f; mem.w = (mem.w > V_TH) ? 0.0f : mem.w;
    out[0 * (size_t)n4 + i] = s;

    // t = 1
    mem.x = TAU * mem.x + x1.x; s.x = (mem.x > V_TH) ? 1.0f : 0.0f; mem.x = (mem.x > V_TH) ? 0.0f : mem.x;
    mem.y = TAU * mem.y + x1.y; s.y = (mem.y > V_TH) ? 1.0f : 0.0f; mem.y = (mem.y > V_TH) ? 0.0f : mem.y;
    mem.z = TAU * mem.z + x1.z; s.z = (mem.z > V_TH) ? 1.0f : 0.0f; mem.z = (mem.z > V_TH) ? 0.0f : mem.z;
    mem.w = TAU * mem.w + x1.w; s.w = (mem.w > V_TH) ? 1.0f : 0.0f; mem.w = (mem.w > V_TH) ? 0.0f : mem.w;
    out[1 * (size_t)n4 + i] = s;

    // t = 2
    mem.x = TAU * mem.x + x2.x; s.x = (mem.x > V_TH) ? 1.0f : 0.0f; mem.x = (mem.x > V_TH) ? 0.0f : mem.x;
    mem.y = TAU * mem.y + x2.y; s.y = (mem.y > V_TH) ? 1.0f : 0.0f; mem.y = (mem.y > V_TH) ? 0.0f : mem.y;
    mem.z = TAU * mem.z + x2.z; s.z = (mem.z > V_TH) ? 1.0f : 0.0f; mem.z = (mem.z > V_TH) ? 0.0f : mem.z;
    mem.w = TAU * mem.w + x2.w; s.w = (mem.w > V_TH) ? 1.0f : 0.0f; mem.w = (mem.w > V_TH) ? 0.0f : mem.w;
    out[2 * (size_t)n4 + i] = s;

    // t = 3
    mem.x = TAU * mem.x + x3.x; s.x = (mem.x > V_TH) ? 1.0f : 0.0f;
    mem.y = TAU * mem.y + x3.y; s.y = (mem.y > V_TH) ? 1.0f : 0.0f;
    mem.z = TAU * mem.z + x3.z; s.z = (mem.z > V_TH) ? 1.0f : 0.0f;
    mem.w = TAU * mem.w + x3.w; s.w = (mem.w > V_TH) ? 1.0f : 0.0f;
    out[3 * (size_t)n4 + i] = s;
}

extern "C" void kernel_launch(void* const* d_in, const int* in_sizes, int n_in,
                              void* d_out, int out_size) {
    const float4* x    = (const float4*)d_in[0];   // [4, 64, 128, 32, 32]
    const float4* mem0 = (const float4*)d_in[1];   // [1, 128, 32, 32]
    float4* out = (float4*)d_out;

    // elements per timestep = total / T
    int n_per_t = in_sizes[0] / 4;       // 8,388,608
    int n4 = n_per_t / 4;                // float4 units: 2,097,152

    int threads = 256;
    int blocks = (n4 + threads - 1) / threads;   // 8192
    lif_kernel<<<blocks, threads>>>(x, mem0, out, n4);
}

// round 2
// speedup vs baseline: 1.0205x; 1.0205x over previous
#include <cuda_runtime.h>
#include <cuda_bf16.h>

// LIF recurrence over T=4 steps.
// x: [T=4, B=64, C=128, H=32, W=32] fp32; mem0: [1, C, H, W] fp32 (B-broadcast)
// out: [T, B, C, H, W] fp32 in {0,1}
// Per element: mem = tau*mem + x[t]; s = (mem > v_th); mem = s ? 0 : mem.
//
// HBM-bound kernel. Each thread handles TWO float4s (at i and i+n4/2):
// 8 front-batched LDG.128 (evict-first streaming) + streaming STG.128.

#define TAU 0.25f
#define V_TH 1.0f
#define T_STEPS 4

__device__ __forceinline__ void lif_step(float4& mem, const float4& xt, float4& s) {
    mem.x = TAU * mem.x + xt.x; s.x = (mem.x > V_TH) ? 1.0f : 0.0f; mem.x = (mem.x > V_TH) ? 0.0f : mem.x;
    mem.y = TAU * mem.y + xt.y; s.y = (mem.y > V_TH) ? 1.0f : 0.0f; mem.y = (mem.y > V_TH) ? 0.0f : mem.y;
    mem.z = TAU * mem.z + xt.z; s.z = (mem.z > V_TH) ? 1.0f : 0.0f; mem.z = (mem.z > V_TH) ? 0.0f : mem.z;
    mem.w = TAU * mem.w + xt.w; s.w = (mem.w > V_TH) ? 1.0f : 0.0f; mem.w = (mem.w > V_TH) ? 0.0f : mem.w;
}

__global__ __launch_bounds__(256) void lif_kernel(
    const float4* __restrict__ x,
    const float4* __restrict__ mem0,
    float4* __restrict__ out,
    int n4)          // float4 units per timestep: B*C*H*W/4 = 2,097,152
{
    int i = blockIdx.x * blockDim.x + threadIdx.x;
    int half = n4 >> 1;                     // 1,048,576
    if (i >= half) return;
    int j = i + half;

    // CHW/4 = 128*32*32/4 = 32768 = 2^15 -> mask for B-broadcast of mem0
    const int CHW4_MASK = 32767;
    float4 memA = __ldg(&mem0[i & CHW4_MASK]);
    float4 memB = __ldg(&mem0[j & CHW4_MASK]);

    // Front-batch all 8 streaming loads (evict-first): 128 B in flight/thread.
    float4 xA[T_STEPS], xB[T_STEPS];
    #pragma unroll
    for (int t = 0; t < T_STEPS; t++) {
        xA[t] = __ldcs(&x[(size_t)t * n4 + i]);
        xB[t] = __ldcs(&x[(size_t)t * n4 + j]);
    }

    #pragma unroll
    for (int t = 0; t < T_STEPS; t++) {
        float4 sA, sB;
        lif_step(memA, xA[t], sA);
        lif_step(memB, xB[t], sB);
        __stcs(&out[(size_t)t * n4 + i], sA);
        __stcs(&out[(size_t)t * n4 + j], sB);
    }
}

extern "C" void kernel_launch(void* const* d_in, const int* in_sizes, int n_in,
                              void* d_out, int out_size) {
    const float4* x    = (const float4*)d_in[0];   // [4, 64, 128, 32, 32]
    const float4* mem0 = (const float4*)d_in[1];   // [1, 128, 32, 32]
    float4* out = (float4*)d_out;

    int n_per_t = in_sizes[0] / 4;       // 8,388,608 elems per timestep
    int n4 = n_per_t / 4;                // 2,097,152 float4 units
    int half = n4 / 2;                   // 1,048,576 threads

    int threads = 256;
    int blocks = (half + threads - 1) / threads;   // 4096
    lif_kernel<<<blocks, threads>>>(x, mem0, out, n4);
}